// round 2
// baseline (speedup 1.0000x reference)
#include <cuda_runtime.h>
#include <cuda_bf16.h>
#include <cstdint>

#define N_NODES 100000
#define N_EDGES 3200000
#define N_FEAT 128
#define DIM 32
#define N_GRAPHS 1024
#define N_CLASSES 10
#define BN_EPS 1e-5f

// ---------------- scratch (static device memory; no allocations) ----------------
__device__ __align__(256) float g_y0[N_NODES * DIM];    // x @ w1a
__device__ __align__(256) float g_agg1[N_NODES * DIM];  // segment_sum(y0[src])
__device__ __align__(256) float g_y2[N_NODES * DIM];    // h1 @ w2a
__device__ __align__(256) float g_agg2[N_NODES * DIM];  // segment_sum(y2[src])
__device__ __align__(256) float g_pooled[N_GRAPHS * DIM];
__device__ __align__(256) int   g_count[N_GRAPHS];

// ---------------- K1: y0 = x @ w1a ; zero agg1/pooled/count ----------------
__global__ __launch_bounds__(256) void k_proj1(const float* __restrict__ x,
                                               const float* __restrict__ w1a) {
    __shared__ float ws[N_FEAT * DIM];  // 16KB
    int tid = threadIdx.x;
    for (int i = tid; i < (N_FEAT * DIM) / 4; i += 256)
        ((float4*)ws)[i] = ((const float4*)w1a)[i];
    __syncthreads();

    int gtid = blockIdx.x * 256 + tid;
    if (gtid < N_GRAPHS * DIM) g_pooled[gtid] = 0.f;
    if (gtid < N_GRAPHS) g_count[gtid] = 0;

    int n = gtid;
    if (n >= N_NODES) return;

    float acc[DIM];
#pragma unroll
    for (int c = 0; c < DIM; c++) acc[c] = 0.f;

    const float4* xr = (const float4*)(x + (size_t)n * N_FEAT);
#pragma unroll 2
    for (int k4 = 0; k4 < N_FEAT / 4; k4++) {
        float4 xv = __ldg(xr + k4);
#pragma unroll
        for (int j = 0; j < 4; j++) {
            float xk = (&xv.x)[j];
            int k = k4 * 4 + j;
#pragma unroll
            for (int c = 0; c < DIM; c++)
                acc[c] = fmaf(xk, ws[k * DIM + c], acc[c]);
        }
    }

    float4* y = (float4*)(g_y0 + (size_t)n * DIM);
    float4* a = (float4*)(g_agg1 + (size_t)n * DIM);
#pragma unroll
    for (int c4 = 0; c4 < DIM / 4; c4++) {
        float4 v = make_float4(acc[c4 * 4 + 0], acc[c4 * 4 + 1],
                               acc[c4 * 4 + 2], acc[c4 * 4 + 3]);
        y[c4] = v;
        a[c4] = make_float4(0.f, 0.f, 0.f, 0.f);
    }
}

// ---------------- K2/K4: edge scatter-add (32-dim, L2-resident) ----------------
// 8 threads per edge; each thread moves one float4 with a vector reduction.
__global__ __launch_bounds__(256) void k_edge(const int* __restrict__ src,
                                              const int* __restrict__ dst,
                                              int pass) {
    const float* __restrict__ yin = (pass == 0) ? g_y0 : g_y2;
    float* agg = (pass == 0) ? g_agg1 : g_agg2;

    unsigned gtid = blockIdx.x * 256u + threadIdx.x;
    unsigned e = gtid >> 3;
    unsigned part = gtid & 7u;
    if (e >= N_EDGES) return;

    int s = __ldg(src + e);
    int d = __ldg(dst + e);

    float4 v = __ldg((const float4*)(yin + (size_t)s * DIM) + part);
    float* p = agg + (size_t)d * DIM + part * 4;
    asm volatile("red.global.add.v4.f32 [%0], {%1,%2,%3,%4};"
                 :: "l"(p), "f"(v.x), "f"(v.y), "f"(v.z), "f"(v.w)
                 : "memory");
}

// ---------------- K3: node update layer1 -> y2 = h1 @ w2a ; zero agg2 ----------------
__global__ __launch_bounds__(256) void k_node1(const float* __restrict__ b1a,
                                               const float* __restrict__ w1b,
                                               const float* __restrict__ b1b,
                                               const float* __restrict__ bn_g,
                                               const float* __restrict__ bn_b,
                                               const float* __restrict__ bn_m,
                                               const float* __restrict__ bn_v,
                                               const float* __restrict__ w2a) {
    __shared__ float w1bs[DIM * DIM], w2as[DIM * DIM];
    __shared__ float b1as[DIM], b1bs[DIM], scs[DIM], shs[DIM];
    int tid = threadIdx.x;
    for (int i = tid; i < DIM * DIM; i += 256) { w1bs[i] = w1b[i]; w2as[i] = w2a[i]; }
    if (tid < DIM) {
        b1as[tid] = b1a[tid];
        b1bs[tid] = b1b[tid];
        float sc = bn_g[tid] * rsqrtf(bn_v[tid] + BN_EPS);
        scs[tid] = sc;
        shs[tid] = bn_b[tid] - bn_m[tid] * sc;
    }
    __syncthreads();

    int lane = tid & 31, warp = tid >> 5;
    int wgid = blockIdx.x * 8 + warp;
    int nwarps = gridDim.x * 8;
    for (int n = wgid; n < N_NODES; n += nwarps) {
        float m = g_y0[n * DIM + lane] + g_agg1[n * DIM + lane] + b1as[lane];
        m = fmaxf(m, 0.f);
        float acc = b1bs[lane];
#pragma unroll
        for (int k = 0; k < DIM; k++)
            acc = fmaf(__shfl_sync(0xffffffffu, m, k), w1bs[k * DIM + lane], acc);
        float h = fmaf(fmaxf(acc, 0.f), scs[lane], shs[lane]);  // bn1(relu(.))
        float acc2 = 0.f;
#pragma unroll
        for (int k = 0; k < DIM; k++)
            acc2 = fmaf(__shfl_sync(0xffffffffu, h, k), w2as[k * DIM + lane], acc2);
        g_y2[n * DIM + lane] = acc2;
        g_agg2[n * DIM + lane] = 0.f;
    }
}

// ---------------- K5: node update layer2 + MLP head + pooled accumulation ----------------
__global__ __launch_bounds__(256) void k_node2(const float* __restrict__ b2a,
                                               const float* __restrict__ w2b,
                                               const float* __restrict__ b2b,
                                               const float* __restrict__ bn_g,
                                               const float* __restrict__ bn_b,
                                               const float* __restrict__ bn_m,
                                               const float* __restrict__ bn_v,
                                               const float* __restrict__ fc1w,
                                               const float* __restrict__ fc1b,
                                               const float* __restrict__ fc2w,
                                               const float* __restrict__ fc2b,
                                               const int* __restrict__ batch) {
    __shared__ float w2bs[DIM * DIM], fc1s[DIM * DIM], fc2s[DIM * DIM];
    __shared__ float b2as[DIM], b2bs[DIM], scs[DIM], shs[DIM], fb1[DIM], fb2[DIM];
    int tid = threadIdx.x;
    for (int i = tid; i < DIM * DIM; i += 256) {
        w2bs[i] = w2b[i]; fc1s[i] = fc1w[i]; fc2s[i] = fc2w[i];
    }
    if (tid < DIM) {
        b2as[tid] = b2a[tid];
        b2bs[tid] = b2b[tid];
        float sc = bn_g[tid] * rsqrtf(bn_v[tid] + BN_EPS);
        scs[tid] = sc;
        shs[tid] = bn_b[tid] - bn_m[tid] * sc;
        fb1[tid] = fc1b[tid];
        fb2[tid] = fc2b[tid];
    }
    __syncthreads();

    int lane = tid & 31, warp = tid >> 5;
    int wgid = blockIdx.x * 8 + warp;
    int nwarps = gridDim.x * 8;
    for (int n = wgid; n < N_NODES; n += nwarps) {
        float m = g_y2[n * DIM + lane] + g_agg2[n * DIM + lane] + b2as[lane];
        m = fmaxf(m, 0.f);
        float acc = b2bs[lane];
#pragma unroll
        for (int k = 0; k < DIM; k++)
            acc = fmaf(__shfl_sync(0xffffffffu, m, k), w2bs[k * DIM + lane], acc);
        float h2 = fmaf(fmaxf(acc, 0.f), scs[lane], shs[lane]);  // bn2(relu(.))
        float a3 = fb1[lane];
#pragma unroll
        for (int k = 0; k < DIM; k++)
            a3 = fmaf(__shfl_sync(0xffffffffu, h2, k), fc1s[k * DIM + lane], a3);
        float h3 = fmaxf(a3, 0.f);
        float h4 = fb2[lane];
#pragma unroll
        for (int k = 0; k < DIM; k++)
            h4 = fmaf(__shfl_sync(0xffffffffu, h3, k), fc2s[k * DIM + lane], h4);

        int g = __ldg(batch + n);
        atomicAdd(&g_pooled[g * DIM + lane], h4);
        if (lane == 0) atomicAdd(&g_count[g], 1);
    }
}

// ---------------- K6: out = (pooled/count) @ lin_w + lin_b ----------------
__global__ __launch_bounds__(256) void k_out(const float* __restrict__ linw,
                                             const float* __restrict__ linb,
                                             float* __restrict__ out) {
    int gw = (blockIdx.x * 256 + threadIdx.x) >> 5;
    int lane = threadIdx.x & 31;
    if (gw >= N_GRAPHS) return;
    float inv = 1.f / fmaxf((float)g_count[gw], 1.f);
    if (lane < N_CLASSES) {
        float acc = linb[lane];
#pragma unroll
        for (int k = 0; k < DIM; k++)
            acc = fmaf(g_pooled[gw * DIM + k] * inv, linw[k * N_CLASSES + lane], acc);
        out[gw * N_CLASSES + lane] = acc;
    }
}

// ---------------- launch ----------------
extern "C" void kernel_launch(void* const* d_in, const int* in_sizes, int n_in,
                              void* d_out, int out_size) {
    const float* x      = (const float*)d_in[0];
    const int*   ei     = (const int*)d_in[1];
    const int*   batch  = (const int*)d_in[2];
    const float* w1a    = (const float*)d_in[3];
    const float* b1a    = (const float*)d_in[4];
    const float* w1b    = (const float*)d_in[5];
    const float* b1b    = (const float*)d_in[6];
    const float* bn1_g  = (const float*)d_in[7];
    const float* bn1_b  = (const float*)d_in[8];
    const float* bn1_m  = (const float*)d_in[9];
    const float* bn1_v  = (const float*)d_in[10];
    const float* w2a    = (const float*)d_in[11];
    const float* b2a    = (const float*)d_in[12];
    const float* w2b    = (const float*)d_in[13];
    const float* b2b    = (const float*)d_in[14];
    const float* bn2_g  = (const float*)d_in[15];
    const float* bn2_b  = (const float*)d_in[16];
    const float* bn2_m  = (const float*)d_in[17];
    const float* bn2_v  = (const float*)d_in[18];
    const float* fc1_w  = (const float*)d_in[19];
    const float* fc1_b  = (const float*)d_in[20];
    const float* fc2_w  = (const float*)d_in[21];
    const float* fc2_b  = (const float*)d_in[22];
    const float* lin_w  = (const float*)d_in[23];
    const float* lin_b  = (const float*)d_in[24];
    float* out = (float*)d_out;

    const int* src = ei;
    const int* dst = ei + N_EDGES;

    int proj_blocks = (N_NODES + 255) / 256;                 // 391 (covers pooled/count zeroing too)
    int edge_blocks = (int)(((long)N_EDGES * 8 + 255) / 256); // 100000
    int node_blocks = 148 * 8;                                // persistent-ish, 8 warps/block

    k_proj1<<<proj_blocks, 256>>>(x, w1a);
    k_edge<<<edge_blocks, 256>>>(src, dst, 0);
    k_node1<<<node_blocks, 256>>>(b1a, w1b, b1b, bn1_g, bn1_b, bn1_m, bn1_v, w2a);
    k_edge<<<edge_blocks, 256>>>(src, dst, 1);
    k_node2<<<node_blocks, 256>>>(b2a, w2b, b2b, bn2_g, bn2_b, bn2_m, bn2_v,
                                  fc1_w, fc1_b, fc2_w, fc2_b, batch);
    k_out<<<N_GRAPHS * 32 / 256, 256>>>(lin_w, lin_b, out);
}

// round 3
// speedup vs baseline: 1.3866x; 1.3866x over previous
#include <cuda_runtime.h>
#include <cuda_bf16.h>
#include <cstdint>

#define N_NODES 100000
#define N_EDGES 3200000
#define N_FEAT 128
#define DIM 32
#define N_GRAPHS 1024
#define N_CLASSES 10
#define BN_EPS 1e-5f

#define NODE_BLOCKS 391  // ceil(100000/256)
#define EDGE_BLOCKS 12500

// ---------------- scratch (static device memory; no allocations) ----------------
__device__ __align__(256) float g_y0[N_NODES * DIM];
__device__ __align__(256) float g_agg1[N_NODES * DIM];
__device__ __align__(256) float g_y2[N_NODES * DIM];
__device__ __align__(256) float g_agg2[N_NODES * DIM];
__device__ __align__(256) float g_pooled[N_GRAPHS * DIM];
__device__ __align__(256) int   g_count[N_GRAPHS];
// CSR scratch
__device__ __align__(256) int g_deg[N_NODES];
__device__ __align__(256) int g_off[N_NODES];
__device__ __align__(256) int g_cur[N_NODES];
__device__ __align__(256) int g_csr[N_EDGES];
__device__ __align__(256) int g_btot[NODE_BLOCKS];

// ---------------- packed f32x2 helpers ----------------
__device__ __forceinline__ unsigned long long fma2(unsigned long long a,
                                                   unsigned long long b,
                                                   unsigned long long c) {
    unsigned long long d;
    asm("fma.rn.f32x2 %0, %1, %2, %3;" : "=l"(d) : "l"(a), "l"(b), "l"(c));
    return d;
}
__device__ __forceinline__ unsigned long long dup2(float x) {
    unsigned long long d;
    asm("mov.b64 %0, {%1, %1};" : "=l"(d) : "f"(x));
    return d;
}
__device__ __forceinline__ void unpack2(unsigned long long v, float& lo, float& hi) {
    asm("mov.b64 {%0, %1}, %2;" : "=f"(lo), "=f"(hi) : "l"(v));
}

// 32x32 matvec: out = m @ W (+bias). W in smem as ull pairs (row-major DIM x DIM floats).
template <bool HAS_BIAS>
__device__ __forceinline__ void matvec32(const float* m,
                                         const unsigned long long* __restrict__ w64,
                                         const unsigned long long* __restrict__ b64,
                                         float* out) {
    unsigned long long acc[16];
#pragma unroll
    for (int cp = 0; cp < 16; cp++) acc[cp] = HAS_BIAS ? b64[cp] : 0ull;
#pragma unroll 4
    for (int k = 0; k < DIM; k++) {
        unsigned long long xx = dup2(m[k]);
#pragma unroll
        for (int cp = 0; cp < 16; cp++)
            acc[cp] = fma2(xx, w64[k * 16 + cp], acc[cp]);
    }
#pragma unroll
    for (int cp = 0; cp < 16; cp++) unpack2(acc[cp], out[2 * cp], out[2 * cp + 1]);
}

// ---------------- K0: zero deg/pooled/count ----------------
__global__ __launch_bounds__(256) void k_zero() {
    int i = blockIdx.x * 256 + threadIdx.x;
    if (i < N_NODES) g_deg[i] = 0;
    if (i < N_GRAPHS * DIM) g_pooled[i] = 0.f;
    if (i < N_GRAPHS) g_count[i] = 0;
}

// ---------------- K_hist: degree histogram over dst ----------------
__global__ __launch_bounds__(256) void k_hist(const int* __restrict__ dst) {
    int e = blockIdx.x * 256 + threadIdx.x;
    if (e < N_EDGES) atomicAdd(&g_deg[__ldg(dst + e)], 1);
}

// ---------------- scan: 3-phase exclusive prefix over g_deg ----------------
__global__ __launch_bounds__(256) void k_scan_a() {
    int t = threadIdx.x, lane = t & 31, w = t >> 5;
    int i = blockIdx.x * 256 + t;
    int v = (i < N_NODES) ? g_deg[i] : 0;
    int incl = v;
#pragma unroll
    for (int d = 1; d < 32; d <<= 1) {
        int x = __shfl_up_sync(0xffffffffu, incl, d);
        if (lane >= d) incl += x;
    }
    __shared__ int wsum[8];
    if (lane == 31) wsum[w] = incl;
    __syncthreads();
    if (t < 8) {
        int s = wsum[t];
#pragma unroll
        for (int d = 1; d < 8; d <<= 1) {
            int x = __shfl_up_sync(0xffu, s, d, 8);
            if (t >= d) s += x;
        }
        wsum[t] = s;
    }
    __syncthreads();
    int blockincl = incl + (w > 0 ? wsum[w - 1] : 0);
    if (i < N_NODES) g_off[i] = blockincl;  // inclusive-in-block, fixed in scan_c
    if (t == 255) g_btot[blockIdx.x] = wsum[7];
}

__global__ __launch_bounds__(512) void k_scan_b() {
    __shared__ int s[512];
    int t = threadIdx.x;
    int v = (t < NODE_BLOCKS) ? g_btot[t] : 0;
    s[t] = v;
    __syncthreads();
    for (int d = 1; d < 512; d <<= 1) {
        int add = (t >= d) ? s[t - d] : 0;
        __syncthreads();
        s[t] += add;
        __syncthreads();
    }
    if (t < NODE_BLOCKS) g_btot[t] = s[t] - v;  // exclusive block base
}

__global__ __launch_bounds__(256) void k_scan_c() {
    int i = blockIdx.x * 256 + threadIdx.x;
    if (i < N_NODES) {
        int ex = g_off[i] - g_deg[i] + g_btot[blockIdx.x];
        g_off[i] = ex;
        g_cur[i] = ex;
    }
}

// ---------------- K_fill: scatter src ids into CSR slots ----------------
__global__ __launch_bounds__(256) void k_fill(const int* __restrict__ src,
                                              const int* __restrict__ dst) {
    int e = blockIdx.x * 256 + threadIdx.x;
    if (e < N_EDGES) {
        int d = __ldg(dst + e);
        int pos = atomicAdd(&g_cur[d], 1);
        g_csr[pos] = __ldg(src + e);
    }
}

// ---------------- K1: y0 = x @ w1a (thread per node, f32x2) ----------------
__global__ __launch_bounds__(256) void k_proj1(const float* __restrict__ x,
                                               const float* __restrict__ w1a) {
    __shared__ float ws[N_FEAT * DIM];  // 16KB
    int tid = threadIdx.x;
    for (int i = tid; i < (N_FEAT * DIM) / 4; i += 256)
        ((float4*)ws)[i] = ((const float4*)w1a)[i];
    __syncthreads();
    const unsigned long long* ws64 = (const unsigned long long*)ws;

    int n = blockIdx.x * 256 + tid;
    if (n >= N_NODES) return;

    unsigned long long acc[16];
#pragma unroll
    for (int cp = 0; cp < 16; cp++) acc[cp] = 0ull;

    const float4* xr = (const float4*)(x + (size_t)n * N_FEAT);
#pragma unroll 2
    for (int k4 = 0; k4 < N_FEAT / 4; k4++) {
        float4 xv = __ldg(xr + k4);
#pragma unroll
        for (int j = 0; j < 4; j++) {
            unsigned long long xx = dup2((&xv.x)[j]);
            int k = k4 * 4 + j;
#pragma unroll
            for (int cp = 0; cp < 16; cp++)
                acc[cp] = fma2(xx, ws64[k * 16 + cp], acc[cp]);
        }
    }
    unsigned long long* y = (unsigned long long*)(g_y0 + (size_t)n * DIM);
#pragma unroll
    for (int cp = 0; cp < 16; cp++) y[cp] = acc[cp];
}

// ---------------- K_agg: CSR gather aggregation (warp = 4 nodes) ----------------
__global__ __launch_bounds__(256) void k_agg(int pass) {
    const float* __restrict__ yin = pass ? g_y2 : g_y0;
    float* aggout = pass ? g_agg2 : g_agg1;

    unsigned wg = (blockIdx.x * 256u + threadIdx.x) >> 5;
    int lane = threadIdx.x & 31;
    int q = lane >> 3, part = lane & 7;
    int n = wg * 4 + q;
    if (n >= N_NODES) return;

    int off = __ldg(&g_off[n]);
    int deg = __ldg(&g_deg[n]);

    float4 a0 = make_float4(0.f, 0.f, 0.f, 0.f);
    float4 a1 = make_float4(0.f, 0.f, 0.f, 0.f);
    int j = 0;
    for (; j + 2 <= deg; j += 2) {
        int i0 = __ldg(&g_csr[off + j]);
        int i1 = __ldg(&g_csr[off + j + 1]);
        float4 v0 = __ldg((const float4*)(yin + (size_t)i0 * DIM) + part);
        float4 v1 = __ldg((const float4*)(yin + (size_t)i1 * DIM) + part);
        a0.x += v0.x; a0.y += v0.y; a0.z += v0.z; a0.w += v0.w;
        a1.x += v1.x; a1.y += v1.y; a1.z += v1.z; a1.w += v1.w;
    }
    if (j < deg) {
        int i0 = __ldg(&g_csr[off + j]);
        float4 v0 = __ldg((const float4*)(yin + (size_t)i0 * DIM) + part);
        a0.x += v0.x; a0.y += v0.y; a0.z += v0.z; a0.w += v0.w;
    }
    float4 r = make_float4(a0.x + a1.x, a0.y + a1.y, a0.z + a1.z, a0.w + a1.w);
    ((float4*)(aggout + (size_t)n * DIM))[part] = r;
}

// ---------------- K3: node update layer1 -> y2 (thread per node) ----------------
__global__ __launch_bounds__(256) void k_node1(const float* __restrict__ b1a,
                                               const float* __restrict__ w1b,
                                               const float* __restrict__ b1b,
                                               const float* __restrict__ bn_g,
                                               const float* __restrict__ bn_b,
                                               const float* __restrict__ bn_m,
                                               const float* __restrict__ bn_v,
                                               const float* __restrict__ w2a) {
    __shared__ float w1bs[DIM * DIM], w2as[DIM * DIM];
    __shared__ float b1as[DIM], b1bs[DIM], scs[DIM], shs[DIM];
    int tid = threadIdx.x;
    for (int i = tid; i < DIM * DIM; i += 256) { w1bs[i] = w1b[i]; w2as[i] = w2a[i]; }
    if (tid < DIM) {
        b1as[tid] = b1a[tid];
        b1bs[tid] = b1b[tid];
        float sc = bn_g[tid] * rsqrtf(bn_v[tid] + BN_EPS);
        scs[tid] = sc;
        shs[tid] = bn_b[tid] - bn_m[tid] * sc;
    }
    __syncthreads();

    int n = blockIdx.x * 256 + tid;
    if (n >= N_NODES) return;

    float m[DIM];
    const float4* yp = (const float4*)(g_y0 + (size_t)n * DIM);
    const float4* ap = (const float4*)(g_agg1 + (size_t)n * DIM);
#pragma unroll
    for (int q = 0; q < 8; q++) {
        float4 a = yp[q], b = ap[q];
        m[4 * q + 0] = fmaxf(a.x + b.x + b1as[4 * q + 0], 0.f);
        m[4 * q + 1] = fmaxf(a.y + b.y + b1as[4 * q + 1], 0.f);
        m[4 * q + 2] = fmaxf(a.z + b.z + b1as[4 * q + 2], 0.f);
        m[4 * q + 3] = fmaxf(a.w + b.w + b1as[4 * q + 3], 0.f);
    }
    float h[DIM];
    matvec32<true>(m, (const unsigned long long*)w1bs, (const unsigned long long*)b1bs, h);
#pragma unroll
    for (int c = 0; c < DIM; c++)
        h[c] = fmaf(fmaxf(h[c], 0.f), scs[c], shs[c]);  // bn1(relu(.))
    float y2v[DIM];
    matvec32<false>(h, (const unsigned long long*)w2as, nullptr, y2v);
    float* yo = g_y2 + (size_t)n * DIM;
#pragma unroll
    for (int q = 0; q < 8; q++)
        ((float4*)yo)[q] = make_float4(y2v[4 * q], y2v[4 * q + 1], y2v[4 * q + 2], y2v[4 * q + 3]);
}

// ---------------- K5: node update layer2 + head + pooling ----------------
__global__ __launch_bounds__(256) void k_node2(const float* __restrict__ b2a,
                                               const float* __restrict__ w2b,
                                               const float* __restrict__ b2b,
                                               const float* __restrict__ bn_g,
                                               const float* __restrict__ bn_b,
                                               const float* __restrict__ bn_m,
                                               const float* __restrict__ bn_v,
                                               const float* __restrict__ fc1w,
                                               const float* __restrict__ fc1b,
                                               const float* __restrict__ fc2w,
                                               const float* __restrict__ fc2b,
                                               const int* __restrict__ batch) {
    __shared__ float w2bs[DIM * DIM], fc1s[DIM * DIM], fc2s[DIM * DIM];
    __shared__ float b2as[DIM], b2bs[DIM], scs[DIM], shs[DIM], fb1[DIM], fb2[DIM];
    int tid = threadIdx.x;
    for (int i = tid; i < DIM * DIM; i += 256) {
        w2bs[i] = w2b[i]; fc1s[i] = fc1w[i]; fc2s[i] = fc2w[i];
    }
    if (tid < DIM) {
        b2as[tid] = b2a[tid];
        b2bs[tid] = b2b[tid];
        float sc = bn_g[tid] * rsqrtf(bn_v[tid] + BN_EPS);
        scs[tid] = sc;
        shs[tid] = bn_b[tid] - bn_m[tid] * sc;
        fb1[tid] = fc1b[tid];
        fb2[tid] = fc2b[tid];
    }
    __syncthreads();

    int n = blockIdx.x * 256 + tid;
    if (n >= N_NODES) return;

    float m[DIM];
    const float4* yp = (const float4*)(g_y2 + (size_t)n * DIM);
    const float4* ap = (const float4*)(g_agg2 + (size_t)n * DIM);
#pragma unroll
    for (int q = 0; q < 8; q++) {
        float4 a = yp[q], b = ap[q];
        m[4 * q + 0] = fmaxf(a.x + b.x + b2as[4 * q + 0], 0.f);
        m[4 * q + 1] = fmaxf(a.y + b.y + b2as[4 * q + 1], 0.f);
        m[4 * q + 2] = fmaxf(a.z + b.z + b2as[4 * q + 2], 0.f);
        m[4 * q + 3] = fmaxf(a.w + b.w + b2as[4 * q + 3], 0.f);
    }
    float h[DIM];
    matvec32<true>(m, (const unsigned long long*)w2bs, (const unsigned long long*)b2bs, h);
#pragma unroll
    for (int c = 0; c < DIM; c++)
        h[c] = fmaf(fmaxf(h[c], 0.f), scs[c], shs[c]);  // bn2(relu(.))
    float h3[DIM];
    matvec32<true>(h, (const unsigned long long*)fc1s, (const unsigned long long*)fb1, h3);
#pragma unroll
    for (int c = 0; c < DIM; c++) h3[c] = fmaxf(h3[c], 0.f);
    float h4[DIM];
    matvec32<true>(h3, (const unsigned long long*)fc2s, (const unsigned long long*)fb2, h4);

    int g = __ldg(batch + n);
    float* pb = g_pooled + (size_t)g * DIM;
#pragma unroll
    for (int q = 0; q < 8; q++) {
        asm volatile("red.global.add.v4.f32 [%0], {%1,%2,%3,%4};"
                     :: "l"(pb + 4 * q), "f"(h4[4 * q]), "f"(h4[4 * q + 1]),
                        "f"(h4[4 * q + 2]), "f"(h4[4 * q + 3])
                     : "memory");
    }
    atomicAdd(&g_count[g], 1);
}

// ---------------- K6: out = (pooled/count) @ lin_w + lin_b ----------------
__global__ __launch_bounds__(256) void k_out(const float* __restrict__ linw,
                                             const float* __restrict__ linb,
                                             float* __restrict__ out) {
    int gw = (blockIdx.x * 256 + threadIdx.x) >> 5;
    int lane = threadIdx.x & 31;
    if (gw >= N_GRAPHS) return;
    float inv = 1.f / fmaxf((float)g_count[gw], 1.f);
    if (lane < N_CLASSES) {
        float acc = linb[lane];
#pragma unroll
        for (int k = 0; k < DIM; k++)
            acc = fmaf(g_pooled[gw * DIM + k] * inv, linw[k * N_CLASSES + lane], acc);
        out[gw * N_CLASSES + lane] = acc;
    }
}

// ---------------- launch ----------------
extern "C" void kernel_launch(void* const* d_in, const int* in_sizes, int n_in,
                              void* d_out, int out_size) {
    const float* x      = (const float*)d_in[0];
    const int*   ei     = (const int*)d_in[1];
    const int*   batch  = (const int*)d_in[2];
    const float* w1a    = (const float*)d_in[3];
    const float* b1a    = (const float*)d_in[4];
    const float* w1b    = (const float*)d_in[5];
    const float* b1b    = (const float*)d_in[6];
    const float* bn1_g  = (const float*)d_in[7];
    const float* bn1_b  = (const float*)d_in[8];
    const float* bn1_m  = (const float*)d_in[9];
    const float* bn1_v  = (const float*)d_in[10];
    const float* w2a    = (const float*)d_in[11];
    const float* b2a    = (const float*)d_in[12];
    const float* w2b    = (const float*)d_in[13];
    const float* b2b    = (const float*)d_in[14];
    const float* bn2_g  = (const float*)d_in[15];
    const float* bn2_b  = (const float*)d_in[16];
    const float* bn2_m  = (const float*)d_in[17];
    const float* bn2_v  = (const float*)d_in[18];
    const float* fc1_w  = (const float*)d_in[19];
    const float* fc1_b  = (const float*)d_in[20];
    const float* fc2_w  = (const float*)d_in[21];
    const float* fc2_b  = (const float*)d_in[22];
    const float* lin_w  = (const float*)d_in[23];
    const float* lin_b  = (const float*)d_in[24];
    float* out = (float*)d_out;

    const int* src = ei;
    const int* dst = ei + N_EDGES;

    int agg_blocks = (25000 + 7) / 8;  // 25000 warps (4 nodes each) / 8 warps per block

    k_zero<<<NODE_BLOCKS, 256>>>();
    k_hist<<<EDGE_BLOCKS, 256>>>(dst);
    k_scan_a<<<NODE_BLOCKS, 256>>>();
    k_scan_b<<<1, 512>>>();
    k_scan_c<<<NODE_BLOCKS, 256>>>();
    k_fill<<<EDGE_BLOCKS, 256>>>(src, dst);
    k_proj1<<<NODE_BLOCKS, 256>>>(x, w1a);
    k_agg<<<agg_blocks, 256>>>(0);
    k_node1<<<NODE_BLOCKS, 256>>>(b1a, w1b, b1b, bn1_g, bn1_b, bn1_m, bn1_v, w2a);
    k_agg<<<agg_blocks, 256>>>(1);
    k_node2<<<NODE_BLOCKS, 256>>>(b2a, w2b, b2b, bn2_g, bn2_b, bn2_m, bn2_v,
                                  fc1_w, fc1_b, fc2_w, fc2_b, batch);
    k_out<<<N_GRAPHS * 32 / 256, 256>>>(lin_w, lin_b, out);
}

// round 5
// speedup vs baseline: 1.4132x; 1.0192x over previous
#include <cuda_runtime.h>
#include <cuda_bf16.h>
#include <cuda_fp16.h>
#include <cstdint>

#define N_NODES 100000
#define N_EDGES 3200000
#define N_FEAT 128
#define DIM 32
#define N_GRAPHS 1024
#define N_CLASSES 10
#define BN_EPS 1e-5f

#define NODE_BLOCKS 391     // ceil(100000/256)
#define EDGE4_BLOCKS 3125   // 3.2M/4/256

// ---------------- scratch (static device memory; no allocations) ----------------
__device__ __align__(256) float  g_y0[N_NODES * DIM];
__device__ __align__(256) float  g_y2[N_NODES * DIM];
__device__ __align__(256) __half g_y0h[N_NODES * DIM];   // fp16 shadow for gathers
__device__ __align__(256) __half g_y2h[N_NODES * DIM];
__device__ __align__(256) float  g_agg1[N_NODES * DIM];
__device__ __align__(256) float  g_agg2[N_NODES * DIM];
__device__ __align__(256) float  g_pooled[N_GRAPHS * DIM];
__device__ __align__(256) int    g_count[N_GRAPHS];
// CSR scratch
__device__ __align__(256) int g_deg[N_NODES];
__device__ __align__(256) int g_off[N_NODES];
__device__ __align__(256) int g_cur[N_NODES];
__device__ __align__(256) int g_csr[N_EDGES];
__device__ __align__(256) int g_btot[NODE_BLOCKS];

// ---------------- packed f32x2 helpers ----------------
__device__ __forceinline__ unsigned long long fma2(unsigned long long a,
                                                   unsigned long long b,
                                                   unsigned long long c) {
    unsigned long long d;
    asm("fma.rn.f32x2 %0, %1, %2, %3;" : "=l"(d) : "l"(a), "l"(b), "l"(c));
    return d;
}
__device__ __forceinline__ unsigned long long dup2(float x) {
    unsigned long long d;
    asm("mov.b64 %0, {%1, %1};" : "=l"(d) : "f"(x));
    return d;
}
__device__ __forceinline__ void unpack2(unsigned long long v, float& lo, float& hi) {
    asm("mov.b64 {%0, %1}, %2;" : "=f"(lo), "=f"(hi) : "l"(v));
}

// 32x32 matvec: out = m @ W (+bias). W in smem as ull pairs.
template <bool HAS_BIAS>
__device__ __forceinline__ void matvec32(const float* m,
                                         const unsigned long long* __restrict__ w64,
                                         const unsigned long long* __restrict__ b64,
                                         float* out) {
    unsigned long long acc[16];
#pragma unroll
    for (int cp = 0; cp < 16; cp++) acc[cp] = HAS_BIAS ? b64[cp] : 0ull;
#pragma unroll 4
    for (int k = 0; k < DIM; k++) {
        unsigned long long xx = dup2(m[k]);
#pragma unroll
        for (int cp = 0; cp < 16; cp++)
            acc[cp] = fma2(xx, w64[k * 16 + cp], acc[cp]);
    }
#pragma unroll
    for (int cp = 0; cp < 16; cp++) unpack2(acc[cp], out[2 * cp], out[2 * cp + 1]);
}

// ---------------- K0: zero deg (int4) ----------------
__global__ __launch_bounds__(256) void k_zero() {
    int i = blockIdx.x * 256 + threadIdx.x;
    if (i < N_NODES / 4) ((int4*)g_deg)[i] = make_int4(0, 0, 0, 0);
}

// ---------------- K1: fused hist (4-wide) + proj1 + pooled/count zero ----------------
__global__ __launch_bounds__(256) void k_histproj(const int* __restrict__ dst,
                                                  const float* __restrict__ x,
                                                  const float* __restrict__ w1a) {
    __shared__ float ws[N_FEAT * DIM];  // 16KB
    int tid = threadIdx.x;
    int bid = blockIdx.x;

    if (bid < EDGE4_BLOCKS) {
        int e4 = bid * 256 + tid;
        int4 d = __ldg((const int4*)dst + e4);
        atomicAdd(&g_deg[d.x], 1);
        atomicAdd(&g_deg[d.y], 1);
        atomicAdd(&g_deg[d.z], 1);
        atomicAdd(&g_deg[d.w], 1);
        return;
    }

    // projection part
    for (int i = tid; i < (N_FEAT * DIM) / 4; i += 256)
        ((float4*)ws)[i] = ((const float4*)w1a)[i];
    __syncthreads();
    const unsigned long long* ws64 = (const unsigned long long*)ws;

    int n = (bid - EDGE4_BLOCKS) * 256 + tid;
    if (n < N_GRAPHS * DIM) g_pooled[n] = 0.f;
    if (n < N_GRAPHS) g_count[n] = 0;
    if (n >= N_NODES) return;

    unsigned long long acc[16];
#pragma unroll
    for (int cp = 0; cp < 16; cp++) acc[cp] = 0ull;

    const float4* xr = (const float4*)(x + (size_t)n * N_FEAT);
#pragma unroll 2
    for (int k4 = 0; k4 < N_FEAT / 4; k4++) {
        float4 xv = __ldg(xr + k4);
#pragma unroll
        for (int j = 0; j < 4; j++) {
            unsigned long long xx = dup2((&xv.x)[j]);
            int k = k4 * 4 + j;
#pragma unroll
            for (int cp = 0; cp < 16; cp++)
                acc[cp] = fma2(xx, ws64[k * 16 + cp], acc[cp]);
        }
    }
    unsigned long long* y = (unsigned long long*)(g_y0 + (size_t)n * DIM);
    __half2 h2[16];
#pragma unroll
    for (int cp = 0; cp < 16; cp++) {
        y[cp] = acc[cp];
        float lo, hi;
        unpack2(acc[cp], lo, hi);
        h2[cp] = __floats2half2_rn(lo, hi);
    }
    uint4* yh = (uint4*)(g_y0h + (size_t)n * DIM);
#pragma unroll
    for (int q = 0; q < 4; q++) yh[q] = ((uint4*)h2)[q];
}

// ---------------- scan ----------------
__global__ __launch_bounds__(256) void k_scan_a() {
    int t = threadIdx.x, lane = t & 31, w = t >> 5;
    int i = blockIdx.x * 256 + t;
    int v = (i < N_NODES) ? g_deg[i] : 0;
    int incl = v;
#pragma unroll
    for (int d = 1; d < 32; d <<= 1) {
        int x = __shfl_up_sync(0xffffffffu, incl, d);
        if (lane >= d) incl += x;
    }
    __shared__ int wsum[8];
    if (lane == 31) wsum[w] = incl;
    __syncthreads();
    if (t < 8) {
        int s = wsum[t];
#pragma unroll
        for (int d = 1; d < 8; d <<= 1) {
            int x = __shfl_up_sync(0xffu, s, d, 8);
            if (t >= d) s += x;
        }
        wsum[t] = s;
    }
    __syncthreads();
    int blockincl = incl + (w > 0 ? wsum[w - 1] : 0);
    if (i < N_NODES) g_off[i] = blockincl;  // inclusive-in-block, fixed in scan_c
    if (t == 255) g_btot[blockIdx.x] = wsum[7];
}

__global__ __launch_bounds__(512) void k_scan_b() {
    int t = threadIdx.x, lane = t & 31, w = t >> 5;  // 16 warps
    int v = (t < NODE_BLOCKS) ? g_btot[t] : 0;
    int incl = v;
#pragma unroll
    for (int d = 1; d < 32; d <<= 1) {
        int x = __shfl_up_sync(0xffffffffu, incl, d);
        if (lane >= d) incl += x;
    }
    __shared__ int wsum[16];
    if (lane == 31) wsum[w] = incl;
    __syncthreads();
    if (t < 16) {
        int s = wsum[t];
#pragma unroll
        for (int d = 1; d < 16; d <<= 1) {
            int x = __shfl_up_sync(0xffffu, s, d, 16);
            if (t >= d) s += x;
        }
        wsum[t] = s;
    }
    __syncthreads();
    int excl = incl - v + (w > 0 ? wsum[w - 1] : 0);
    if (t < NODE_BLOCKS) g_btot[t] = excl;
}

__global__ __launch_bounds__(256) void k_scan_c() {
    int i = blockIdx.x * 256 + threadIdx.x;
    if (i < N_NODES) {
        int ex = g_off[i] - g_deg[i] + g_btot[blockIdx.x];
        g_off[i] = ex;
        g_cur[i] = ex;
    }
}

// ---------------- K_fill: scatter src ids into CSR slots (4-wide) ----------------
__global__ __launch_bounds__(256) void k_fill(const int* __restrict__ src,
                                              const int* __restrict__ dst) {
    int e4 = blockIdx.x * 256 + threadIdx.x;
    int4 s = __ldg((const int4*)src + e4);
    int4 d = __ldg((const int4*)dst + e4);
    g_csr[atomicAdd(&g_cur[d.x], 1)] = s.x;
    g_csr[atomicAdd(&g_cur[d.y], 1)] = s.y;
    g_csr[atomicAdd(&g_cur[d.z], 1)] = s.z;
    g_csr[atomicAdd(&g_cur[d.w], 1)] = s.w;
}

// ---------------- K_agg: warp-per-node fp16 gather ----------------
__global__ __launch_bounds__(256) void k_agg(int pass) {
    const __half* __restrict__ yin = pass ? g_y2h : g_y0h;
    float* aggout = pass ? g_agg2 : g_agg1;

    int n = (int)((blockIdx.x * 256u + threadIdx.x) >> 5);
    if (n >= N_NODES) return;
    int lane = threadIdx.x & 31;
    int grp = lane >> 2;   // neighbor slot 0..7
    int part = lane & 3;   // 16B chunk of 64B row

    int off = __ldg(&g_off[n]);
    int deg = __ldg(&g_deg[n]);

    float acc[8];
#pragma unroll
    for (int t = 0; t < 8; t++) acc[t] = 0.f;

    for (int j = grp; j < deg; j += 8) {
        int idx = __ldg(&g_csr[off + j]);
        uint4 v = __ldg((const uint4*)(yin + (size_t)idx * DIM) + part);
        const __half2* hv = (const __half2*)&v;
#pragma unroll
        for (int t = 0; t < 4; t++) {
            float2 f = __half22float2(hv[t]);
            acc[2 * t] += f.x;
            acc[2 * t + 1] += f.y;
        }
    }
    // reduce across the 8 neighbor groups (lanes differing in grp bits)
#pragma unroll
    for (int o = 4; o < 32; o <<= 1) {
#pragma unroll
        for (int t = 0; t < 8; t++)
            acc[t] += __shfl_xor_sync(0xffffffffu, acc[t], o);
    }
    if (grp == 0) {
        float4* row = (float4*)(aggout + (size_t)n * DIM);
        row[part * 2]     = make_float4(acc[0], acc[1], acc[2], acc[3]);
        row[part * 2 + 1] = make_float4(acc[4], acc[5], acc[6], acc[7]);
    }
}

// ---------------- K3: node update layer1 -> y2 (+fp16 shadow) ----------------
__global__ __launch_bounds__(256) void k_node1(const float* __restrict__ b1a,
                                               const float* __restrict__ w1b,
                                               const float* __restrict__ b1b,
                                               const float* __restrict__ bn_g,
                                               const float* __restrict__ bn_b,
                                               const float* __restrict__ bn_m,
                                               const float* __restrict__ bn_v,
                                               const float* __restrict__ w2a) {
    __shared__ float w1bs[DIM * DIM], w2as[DIM * DIM];
    __shared__ float b1as[DIM], b1bs[DIM], scs[DIM], shs[DIM];
    int tid = threadIdx.x;
    for (int i = tid; i < DIM * DIM; i += 256) { w1bs[i] = w1b[i]; w2as[i] = w2a[i]; }
    if (tid < DIM) {
        b1as[tid] = b1a[tid];
        b1bs[tid] = b1b[tid];
        float sc = bn_g[tid] * rsqrtf(bn_v[tid] + BN_EPS);
        scs[tid] = sc;
        shs[tid] = bn_b[tid] - bn_m[tid] * sc;
    }
    __syncthreads();

    int n = blockIdx.x * 256 + tid;
    if (n >= N_NODES) return;

    float m[DIM];
    const float4* yp = (const float4*)(g_y0 + (size_t)n * DIM);
    const float4* ap = (const float4*)(g_agg1 + (size_t)n * DIM);
#pragma unroll
    for (int q = 0; q < 8; q++) {
        float4 a = yp[q], b = ap[q];
        m[4 * q + 0] = fmaxf(a.x + b.x + b1as[4 * q + 0], 0.f);
        m[4 * q + 1] = fmaxf(a.y + b.y + b1as[4 * q + 1], 0.f);
        m[4 * q + 2] = fmaxf(a.z + b.z + b1as[4 * q + 2], 0.f);
        m[4 * q + 3] = fmaxf(a.w + b.w + b1as[4 * q + 3], 0.f);
    }
    float h[DIM];
    matvec32<true>(m, (const unsigned long long*)w1bs, (const unsigned long long*)b1bs, h);
#pragma unroll
    for (int c = 0; c < DIM; c++)
        h[c] = fmaf(fmaxf(h[c], 0.f), scs[c], shs[c]);  // bn1(relu(.))
    float y2v[DIM];
    matvec32<false>(h, (const unsigned long long*)w2as, nullptr, y2v);

    float* yo = g_y2 + (size_t)n * DIM;
    __half2 h2[16];
#pragma unroll
    for (int q = 0; q < 8; q++)
        ((float4*)yo)[q] = make_float4(y2v[4 * q], y2v[4 * q + 1], y2v[4 * q + 2], y2v[4 * q + 3]);
#pragma unroll
    for (int cp = 0; cp < 16; cp++)
        h2[cp] = __floats2half2_rn(y2v[2 * cp], y2v[2 * cp + 1]);
    uint4* yh = (uint4*)(g_y2h + (size_t)n * DIM);
#pragma unroll
    for (int q = 0; q < 4; q++) yh[q] = ((uint4*)h2)[q];
}

// ---------------- K5: node update layer2 + head + pooling ----------------
__global__ __launch_bounds__(256) void k_node2(const float* __restrict__ b2a,
                                               const float* __restrict__ w2b,
                                               const float* __restrict__ b2b,
                                               const float* __restrict__ bn_g,
                                               const float* __restrict__ bn_b,
                                               const float* __restrict__ bn_m,
                                               const float* __restrict__ bn_v,
                                               const float* __restrict__ fc1w,
                                               const float* __restrict__ fc1b,
                                               const float* __restrict__ fc2w,
                                               const float* __restrict__ fc2b,
                                               const int* __restrict__ batch) {
    __shared__ float w2bs[DIM * DIM], fc1s[DIM * DIM], fc2s[DIM * DIM];
    __shared__ float b2as[DIM], b2bs[DIM], scs[DIM], shs[DIM], fb1[DIM], fb2[DIM];
    int tid = threadIdx.x;
    for (int i = tid; i < DIM * DIM; i += 256) {
        w2bs[i] = w2b[i]; fc1s[i] = fc1w[i]; fc2s[i] = fc2w[i];
    }
    if (tid < DIM) {
        b2as[tid] = b2a[tid];
        b2bs[tid] = b2b[tid];
        float sc = bn_g[tid] * rsqrtf(bn_v[tid] + BN_EPS);
        scs[tid] = sc;
        shs[tid] = bn_b[tid] - bn_m[tid] * sc;
        fb1[tid] = fc1b[tid];
        fb2[tid] = fc2b[tid];
    }
    __syncthreads();

    int n = blockIdx.x * 256 + tid;
    if (n >= N_NODES) return;

    float m[DIM];
    const float4* yp = (const float4*)(g_y2 + (size_t)n * DIM);
    const float4* ap = (const float4*)(g_agg2 + (size_t)n * DIM);
#pragma unroll
    for (int q = 0; q < 8; q++) {
        float4 a = yp[q], b = ap[q];
        m[4 * q + 0] = fmaxf(a.x + b.x + b2as[4 * q + 0], 0.f);
        m[4 * q + 1] = fmaxf(a.y + b.y + b2as[4 * q + 1], 0.f);
        m[4 * q + 2] = fmaxf(a.z + b.z + b2as[4 * q + 2], 0.f);
        m[4 * q + 3] = fmaxf(a.w + b.w + b2as[4 * q + 3], 0.f);
    }
    float h[DIM];
    matvec32<true>(m, (const unsigned long long*)w2bs, (const unsigned long long*)b2bs, h);
#pragma unroll
    for (int c = 0; c < DIM; c++)
        h[c] = fmaf(fmaxf(h[c], 0.f), scs[c], shs[c]);  // bn2(relu(.))
    float h3[DIM];
    matvec32<true>(h, (const unsigned long long*)fc1s, (const unsigned long long*)fb1, h3);
#pragma unroll
    for (int c = 0; c < DIM; c++) h3[c] = fmaxf(h3[c], 0.f);
    float h4[DIM];
    matvec32<true>(h3, (const unsigned long long*)fc2s, (const unsigned long long*)fb2, h4);

    int g = __ldg(batch + n);
    float* pb = g_pooled + (size_t)g * DIM;
#pragma unroll
    for (int q = 0; q < 8; q++) {
        asm volatile("red.global.add.v4.f32 [%0], {%1,%2,%3,%4};"
                     :: "l"(pb + 4 * q), "f"(h4[4 * q]), "f"(h4[4 * q + 1]),
                        "f"(h4[4 * q + 2]), "f"(h4[4 * q + 3])
                     : "memory");
    }
    atomicAdd(&g_count[g], 1);
}

// ---------------- K6: out = (pooled/count) @ lin_w + lin_b ----------------
__global__ __launch_bounds__(256) void k_out(const float* __restrict__ linw,
                                             const float* __restrict__ linb,
                                             float* __restrict__ out) {
    int gw = (blockIdx.x * 256 + threadIdx.x) >> 5;
    int lane = threadIdx.x & 31;
    if (gw >= N_GRAPHS) return;
    float inv = 1.f / fmaxf((float)g_count[gw], 1.f);
    if (lane < N_CLASSES) {
        float acc = linb[lane];
#pragma unroll
        for (int k = 0; k < DIM; k++)
            acc = fmaf(g_pooled[gw * DIM + k] * inv, linw[k * N_CLASSES + lane], acc);
        out[gw * N_CLASSES + lane] = acc;
    }
}

// ---------------- launch ----------------
extern "C" void kernel_launch(void* const* d_in, const int* in_sizes, int n_in,
                              void* d_out, int out_size) {
    const float* x      = (const float*)d_in[0];
    const int*   ei     = (const int*)d_in[1];
    const int*   batch  = (const int*)d_in[2];
    const float* w1a    = (const float*)d_in[3];
    const float* b1a    = (const float*)d_in[4];
    const float* w1b    = (const float*)d_in[5];
    const float* b1b    = (const float*)d_in[6];
    const float* bn1_g  = (const float*)d_in[7];
    const float* bn1_b  = (const float*)d_in[8];
    const float* bn1_m  = (const float*)d_in[9];
    const float* bn1_v  = (const float*)d_in[10];
    const float* w2a    = (const float*)d_in[11];
    const float* b2a    = (const float*)d_in[12];
    const float* w2b    = (const float*)d_in[13];
    const float* b2b    = (const float*)d_in[14];
    const float* bn2_g  = (const float*)d_in[15];
    const float* bn2_b  = (const float*)d_in[16];
    const float* bn2_m  = (const float*)d_in[17];
    const float* bn2_v  = (const float*)d_in[18];
    const float* fc1_w  = (const float*)d_in[19];
    const float* fc1_b  = (const float*)d_in[20];
    const float* fc2_w  = (const float*)d_in[21];
    const float* fc2_b  = (const float*)d_in[22];
    const float* lin_w  = (const float*)d_in[23];
    const float* lin_b  = (const float*)d_in[24];
    float* out = (float*)d_out;

    const int* src = ei;
    const int* dst = ei + N_EDGES;

    int agg_blocks = (N_NODES + 7) / 8;  // warp per node, 8 warps/block

    k_zero<<<(N_NODES / 4 + 255) / 256, 256>>>();
    k_histproj<<<EDGE4_BLOCKS + NODE_BLOCKS, 256>>>(dst, x, w1a);
    k_scan_a<<<NODE_BLOCKS, 256>>>();
    k_scan_b<<<1, 512>>>();
    k_scan_c<<<NODE_BLOCKS, 256>>>();
    k_fill<<<EDGE4_BLOCKS, 256>>>(src, dst);
    k_agg<<<agg_blocks, 256>>>(0);
    k_node1<<<NODE_BLOCKS, 256>>>(b1a, w1b, b1b, bn1_g, bn1_b, bn1_m, bn1_v, w2a);
    k_agg<<<agg_blocks, 256>>>(1);
    k_node2<<<NODE_BLOCKS, 256>>>(b2a, w2b, b2b, bn2_g, bn2_b, bn2_m, bn2_v,
                                  fc1_w, fc1_b, fc2_w, fc2_b, batch);
    k_out<<<N_GRAPHS * 32 / 256, 256>>>(lin_w, lin_b, out);
}